// round 1
// baseline (speedup 1.0000x reference)
#include <cuda_runtime.h>

// loss = sum_{rows, j>=1} relu(|x[:,j] - x[:,j-1]| - 1) * mask[:,j]
// x, mask: [65536, 512] fp32. Pure HBM-streaming reduction: 256 MB read.

#define ROW_LEN       512
#define ROW_F4        128                    // float4s per row
#define THREADS       256
#define BLOCKS        2048                   // 524288 threads; 8388608/524288 = 16 iters exactly

__global__ void zero_out_kernel(float* out) {
    if (threadIdx.x == 0 && blockIdx.x == 0) out[0] = 0.0f;
}

__global__ __launch_bounds__(THREADS)
void connect_loss_kernel(const float* __restrict__ x,
                         const float* __restrict__ mask,
                         float* __restrict__ out,
                         long long n4) {
    const float4* __restrict__ x4 = reinterpret_cast<const float4*>(x);
    const float4* __restrict__ m4 = reinterpret_cast<const float4*>(mask);

    const long long stride = (long long)gridDim.x * blockDim.x;
    long long i = (long long)blockIdx.x * blockDim.x + threadIdx.x;
    const int lane = threadIdx.x & 31;

    float s = 0.0f;

    for (; i < n4; i += stride) {
        float4 v = x4[i];
        float4 m = m4[i];

        // previous element: lane-1's v.w (contiguous float4 -> contiguous lane).
        float prev = __shfl_up_sync(0xffffffffu, v.w, 1);

        int c = (int)(i & (ROW_F4 - 1));     // float4 position within row
        // Only lane 0 can have c==0 (row start) or need a cross-warp neighbor,
        // because ROW_F4 (128) is a multiple of warp size and i is lane-contiguous.
        if (lane == 0 && c != 0) {
            prev = x[4 * i - 1];
        }

        float acc;
        // column 0 of each row contributes 0 (pad); c==0 only occurs at lane 0.
        float d0 = fmaxf(fabsf(v.x - prev) - 1.0f, 0.0f) * m.x;
        acc  = (c != 0) ? d0 : 0.0f;
        acc += fmaxf(fabsf(v.y - v.x) - 1.0f, 0.0f) * m.y;
        acc += fmaxf(fabsf(v.z - v.y) - 1.0f, 0.0f) * m.z;
        acc += fmaxf(fabsf(v.w - v.z) - 1.0f, 0.0f) * m.w;
        s += acc;
    }

    // warp reduction
    #pragma unroll
    for (int o = 16; o > 0; o >>= 1)
        s += __shfl_xor_sync(0xffffffffu, s, o);

    __shared__ float smem[THREADS / 32];
    int w = threadIdx.x >> 5;
    if (lane == 0) smem[w] = s;
    __syncthreads();

    if (w == 0) {
        s = (lane < (THREADS / 32)) ? smem[lane] : 0.0f;
        #pragma unroll
        for (int o = 16; o > 0; o >>= 1)
            s += __shfl_xor_sync(0xffffffffu, s, o);
        if (lane == 0) atomicAdd(out, s);
    }
}

extern "C" void kernel_launch(void* const* d_in, const int* in_sizes, int n_in,
                              void* d_out, int out_size) {
    const float* x    = (const float*)d_in[0];
    const float* mask = (const float*)d_in[1];
    float* out = (float*)d_out;

    long long n  = (long long)in_sizes[0];   // 65536 * 512
    long long n4 = n / 4;

    zero_out_kernel<<<1, 32>>>(out);
    connect_loss_kernel<<<BLOCKS, THREADS>>>(x, mask, out, n4);
}

// round 2
// speedup vs baseline: 1.0425x; 1.0425x over previous
#include <cuda_runtime.h>

// loss = sum_{rows, j>=1} relu(|x[:,j] - x[:,j-1]| - 1) * mask[:,j]
// x, mask: [65536, 512] fp32. Pure HBM-streaming reduction: 256 MB read, 4 B out.

#define THREADS   256
#define BLOCKS    1024          // single wave on 148 SMs (<= 8 blocks/SM capacity)
#define ITERS     32            // 8388608 float4s / (1024*256) == 32 exactly
#define ROW_F4    128           // float4s per 512-float row

__device__ float        g_partials[BLOCKS];
__device__ unsigned int g_ticket = 0;       // zero-initialized; reset by last block each run

__global__ __launch_bounds__(THREADS)
void connect_loss_kernel(const float* __restrict__ x,
                         const float* __restrict__ mask,
                         float* __restrict__ out) {
    const float4* __restrict__ x4 = reinterpret_cast<const float4*>(x);
    const float4* __restrict__ m4 = reinterpret_cast<const float4*>(mask);

    const long long stride = (long long)BLOCKS * THREADS;   // multiple of ROW_F4
    long long i = (long long)blockIdx.x * THREADS + threadIdx.x;
    const int lane = threadIdx.x & 31;
    // position-in-row is loop-invariant: stride % 128 == 0
    const int c = (int)(i & (ROW_F4 - 1));
    const bool fixup = (lane == 0) && (c != 0);   // lane 0 mid-row: cross-warp neighbor
    const bool rowstart = (c == 0);               // column 0 contributes 0

    float s = 0.0f;

    #pragma unroll 4
    for (int it = 0; it < ITERS; ++it, i += stride) {
        float4 v = x4[i];
        float4 m = m4[i];

        // previous element lives in lane-1's v.w (contiguous float4 -> contiguous lane)
        float prev = __shfl_up_sync(0xffffffffu, v.w, 1);
        if (fixup) prev = x[4 * i - 1];

        float d0 = fmaxf(fabsf(v.x - prev) - 1.0f, 0.0f) * m.x;
        float acc = rowstart ? 0.0f : d0;
        acc += fmaxf(fabsf(v.y - v.x) - 1.0f, 0.0f) * m.y;
        acc += fmaxf(fabsf(v.z - v.y) - 1.0f, 0.0f) * m.z;
        acc += fmaxf(fabsf(v.w - v.z) - 1.0f, 0.0f) * m.w;
        s += acc;
    }

    // ---- block reduction ----
    __shared__ float smem[THREADS / 32];
    __shared__ bool  amLast;

    #pragma unroll
    for (int o = 16; o > 0; o >>= 1)
        s += __shfl_xor_sync(0xffffffffu, s, o);

    int w = threadIdx.x >> 5;
    if (lane == 0) smem[w] = s;
    __syncthreads();

    if (threadIdx.x == 0) {
        float bs = 0.0f;
        #pragma unroll
        for (int k = 0; k < THREADS / 32; ++k) bs += smem[k];
        g_partials[blockIdx.x] = bs;
        __threadfence();
        unsigned int t = atomicAdd(&g_ticket, 1u);
        amLast = (t == BLOCKS - 1);
    }
    __syncthreads();

    // ---- last block: final deterministic reduction over 1024 partials ----
    if (amLast) {
        __threadfence();   // ensure all partials visible
        float v = 0.0f;
        #pragma unroll
        for (int k = 0; k < BLOCKS / THREADS; ++k)
            v += g_partials[threadIdx.x + k * THREADS];

        #pragma unroll
        for (int o = 16; o > 0; o >>= 1)
            v += __shfl_xor_sync(0xffffffffu, v, o);

        if (lane == 0) smem[w] = v;
        __syncthreads();

        if (threadIdx.x == 0) {
            float total = 0.0f;
            #pragma unroll
            for (int k = 0; k < THREADS / 32; ++k) total += smem[k];
            out[0] = total;
            g_ticket = 0;          // reset for next graph replay
        }
    }
}

extern "C" void kernel_launch(void* const* d_in, const int* in_sizes, int n_in,
                              void* d_out, int out_size) {
    const float* x    = (const float*)d_in[0];
    const float* mask = (const float*)d_in[1];
    float* out = (float*)d_out;

    connect_loss_kernel<<<BLOCKS, THREADS>>>(x, mask, out);
}